// round 4
// baseline (speedup 1.0000x reference)
#include <cuda_runtime.h>

// Problem constants (fixed by the reference)
#define NB        2000                  // N_BUSES
#define BATCH     32                    // B
#define NEDGE     6000                  // E per batch
#define TOT_NODES (BATCH * NB)          // 64000
#define TOT_EDGES (BATCH * NEDGE)       // 192000
#define HSLOTS    8192                  // per-batch hash slots (pow2, load 0.73)
#define HMASK     (HSLOTS - 1)
#define NTHR1     1024                  // K1 block size
#define NTHR2     256                   // K2 block size
#define NBLK2     ((TOT_NODES + NTHR2 - 1) / NTHR2)   // 250

// Static scratch (no allocations allowed)
__device__ unsigned long long g_hash[BATCH * HSLOTS]; // 2 MB: (cell+1)<<32 | edge_id
__device__ float2             g_yv[TOT_NODES];        // YV (complex), written by K1
__device__ double             g_acc[5];               // d1r, d1i, d2, d3, mse
__device__ unsigned           g_count;                // last-block counter

__device__ __forceinline__ unsigned hash_cell(unsigned cell) {
    return (cell * 2654435761u) >> (32 - 13);         // 13 = log2(HSLOTS)
}

// ============================ K1: per-batch dedup + scatter =================
// Block b exclusively owns g_hash[b] and batch b's YV -> __syncthreads suffices.
__global__ __launch_bounds__(NTHR1)
void k_build(const float* __restrict__ ea,
             const int*   __restrict__ ei,
             const float* __restrict__ outs) {
    __shared__ float2 V[NB];      // 16 KB
    __shared__ float2 YV[NB];     // 16 KB
    const int b   = blockIdx.x;
    const int tid = threadIdx.x;
    unsigned long long* tab = g_hash + (size_t)b * HSLOTS;
    const float2* outs2 = (const float2*)outs;

    // clear hash (global, own region), stage V, clear YV (smem)
    #pragma unroll
    for (int s = tid; s < HSLOTS; s += NTHR1) tab[s] = 0ULL;
    for (int n = tid; n < NB; n += NTHR1) {
        V[n]  = outs2[b * NB + n];
        YV[n] = make_float2(0.f, 0.f);
    }
    if (b == 0 && tid < 6) {                 // reset accumulators + counter
        if (tid < 5) g_acc[tid] = 0.0;
        else         g_count    = 0u;
    }
    __syncthreads();

    // pass 1: last-write-wins insert (JAX .set: max edge id per cell wins)
    for (int e = tid; e < NEDGE; e += NTHR1) {
        int t = b * NEDGE + e;
        int i = ei[t] % NB;              if (i < 0) i += NB;
        int j = ei[TOT_EDGES + t] % NB;  if (j < 0) j += NB;
        unsigned cell = (unsigned)(i * NB + j) + 1u;         // +1: 0 == empty
        unsigned long long mine = ((unsigned long long)cell << 32) | (unsigned)e;
        unsigned h = hash_cell(cell);
        while (true) {
            unsigned long long old = atomicCAS(&tab[h], 0ULL, mine);
            if (old == 0ULL) break;
            if ((unsigned)(old >> 32) == cell) { atomicMax(&tab[h], mine); break; }
            h = (h + 1) & HMASK;
        }
    }
    __syncthreads();

    // pass 2: scan slots (L2 reads: atomics committed in L2, L1 may be stale),
    // scatter adm*V[j] into smem YV[i] for each unique winning cell.
    for (int s = tid; s < HSLOTS; s += NTHR1) {
        unsigned long long ent = __ldcg(&tab[s]);
        if (ent == 0ULL) continue;
        unsigned cell = (unsigned)(ent >> 32) - 1u;
        int e = (int)(unsigned)ent;
        int i = (int)(cell / NB);
        int j = (int)(cell - (unsigned)i * NB);
        float2 adm = ((const float2*)ea)[b * NEDGE + e];
        float2 v = V[j];
        atomicAdd(&YV[i].x, adm.x * v.x - adm.y * v.y);
        atomicAdd(&YV[i].y, adm.x * v.y + adm.y * v.x);
    }
    __syncthreads();

    // dump YV to global for K2 (coalesced)
    for (int n = tid; n < NB; n += NTHR1) g_yv[b * NB + n] = YV[n];
}

// ===================== K2: node terms + reduce + finalize ===================
// Output: 5 float32 = real parts of (loss, physics_loss, d1, d2, d3).
__global__ __launch_bounds__(NTHR2)
void k_node(const float* __restrict__ x,
            const float* __restrict__ outs,
            const float* __restrict__ labels,
            float* __restrict__ out, int nfloats) {
    int idx = blockIdx.x * NTHR2 + threadIdx.x;
    double a0 = 0, a1 = 0, a2 = 0, a3 = 0, a4 = 0;

    if (idx < TOT_NODES) {
        float2 v  = ((const float2*)outs)[idx];
        float2 yv = g_yv[idx];
        // Spred = V * conj(YV)
        float spr = v.x * yv.x + v.y * yv.y;
        float spi = v.y * yv.x - v.x * yv.y;

        const float2* nf2 = (const float2*)(x + 6 * idx);
        float2 p0 = nf2[0], p1 = nf2[1], p2 = nf2[2];
        float sr = p0.x, si = p0.y, Vm = p1.x;
        float b0 = p1.y, b1 = p2.x, b2 = p2.y;

        float dr = spr - sr;
        float di = spi - si;
        float sinv = rsqrtf(sr * sr + si * si);              // |1/S|

        a0 = (double)(sinv * ((dr * dr - di * di) * b0 + dr * dr * b1));
        a1 = (double)(sinv * (2.f * dr * di * b0));

        float vmag  = sqrtf(v.x * v.x + v.y * v.y);
        float vminv = 1.f / Vm;
        a2 = (double)(fabsf(vmag * (b1 + b2) - Vm) * vminv);
        a3 = (double)(fabsf(v.y * b2) * vminv);

        float2 lab = ((const float2*)labels)[idx];
        float e0 = v.x - lab.x;
        float e1 = v.y - lab.y;
        a4 = (double)(e0 * e0) + (double)(e1 * e1);
    }

    // warp reduce
    #pragma unroll
    for (int o = 16; o > 0; o >>= 1) {
        a0 += __shfl_down_sync(0xFFFFFFFFu, a0, o);
        a1 += __shfl_down_sync(0xFFFFFFFFu, a1, o);
        a2 += __shfl_down_sync(0xFFFFFFFFu, a2, o);
        a3 += __shfl_down_sync(0xFFFFFFFFu, a3, o);
        a4 += __shfl_down_sync(0xFFFFFFFFu, a4, o);
    }

    __shared__ double sm[5][8];
    __shared__ bool   last;
    int lane = threadIdx.x & 31, warp = threadIdx.x >> 5;
    if (lane == 0) { sm[0][warp] = a0; sm[1][warp] = a1; sm[2][warp] = a2;
                     sm[3][warp] = a3; sm[4][warp] = a4; }
    __syncthreads();
    if (warp == 0) {
        double v0 = (lane < 8) ? sm[0][lane] : 0.0;
        double v1 = (lane < 8) ? sm[1][lane] : 0.0;
        double v2 = (lane < 8) ? sm[2][lane] : 0.0;
        double v3 = (lane < 8) ? sm[3][lane] : 0.0;
        double v4 = (lane < 8) ? sm[4][lane] : 0.0;
        #pragma unroll
        for (int o = 4; o > 0; o >>= 1) {
            v0 += __shfl_down_sync(0xFFFFFFFFu, v0, o);
            v1 += __shfl_down_sync(0xFFFFFFFFu, v1, o);
            v2 += __shfl_down_sync(0xFFFFFFFFu, v2, o);
            v3 += __shfl_down_sync(0xFFFFFFFFu, v3, o);
            v4 += __shfl_down_sync(0xFFFFFFFFu, v4, o);
        }
        if (lane == 0) {
            atomicAdd(&g_acc[0], v0);
            atomicAdd(&g_acc[1], v1);
            atomicAdd(&g_acc[2], v2);
            atomicAdd(&g_acc[3], v3);
            atomicAdd(&g_acc[4], v4);
            __threadfence();
            unsigned r = atomicAdd(&g_count, 1u);
            last = (r == (unsigned)(gridDim.x - 1));
        }
    }
    __syncthreads();

    // last block finalizes
    if (last && threadIdx.x == 0) {
        double v0 = __longlong_as_double(__ldcg((const long long*)&g_acc[0]));
        double v1 = __longlong_as_double(__ldcg((const long long*)&g_acc[1]));
        double v2 = __longlong_as_double(__ldcg((const long long*)&g_acc[2]));
        double v3 = __longlong_as_double(__ldcg((const long long*)&g_acc[3]));
        double v4 = __longlong_as_double(__ldcg((const long long*)&g_acc[4]));
        const double inv = 1.0 / (double)TOT_NODES;
        double d1r = v0 * inv;
        double d1i = v1 * inv;
        double d2  = v2 * inv;
        double d3  = v3 * inv;
        double mse = v4 / (double)(TOT_NODES * 2);
        double pr  = d1r + d2 + d3;
        double lr  = mse + 0.1 * pr;
        float vals[10] = { (float)lr, (float)pr, (float)d1r, (float)d2, (float)d3,
                           (float)(0.1 * d1i), (float)d1i, (float)d1i, 0.f, 0.f };
        for (int k = 0; k < nfloats && k < 10; k++) out[k] = vals[k];
    }
}

// ------------------------------------------------------------------ launcher
extern "C" void kernel_launch(void* const* d_in, const int* in_sizes, int n_in,
                              void* d_out, int out_size) {
    const float* x      = (const float*)d_in[0];   // (B*2000, 6)
    const float* ea     = (const float*)d_in[1];   // (B*6000, 2)
    const int*   ei     = (const int*)  d_in[2];   // (2, B*6000)
    const float* outs   = (const float*)d_in[3];   // (B*2000, 2)
    const float* labels = (const float*)d_in[4];   // (B*2000, 2)
    (void)in_sizes; (void)n_in;

    int nfloats = out_size < 10 ? out_size : 10;

    k_build<<<BATCH, NTHR1>>>(ea, ei, outs);
    k_node <<<NBLK2, NTHR2>>>(x, outs, labels, (float*)d_out, nfloats);
}

// round 5
// speedup vs baseline: 1.4872x; 1.4872x over previous
#include <cuda_runtime.h>

// Problem constants (fixed by the reference)
#define NB        2000                  // N_BUSES
#define BATCH     32                    // B
#define NEDGE     6000                  // E per batch
#define TOT_NODES (BATCH * NB)          // 64000
#define TOT_EDGES (BATCH * NEDGE)       // 192000
#define HSLOTS    8192                  // per-batch hash slots (pow2, load ~0.73)
#define HMASK     (HSLOTS - 1)
#define HLOG2     13
#define TOT_SLOTS (BATCH * HSLOTS)      // 262144

// Static scratch — zero at module load; every kernel self-cleans what it used,
// so each kernel_launch call starts from zeroed state (deterministic).
__device__ unsigned long long g_hash[TOT_SLOTS];  // 2 MB: (cell+1)<<32 | edge_id
__device__ float2             g_yv[TOT_NODES];    // YV (complex)
__device__ float              g_acc[5];           // d1r, d1i, d2, d3, mse
__device__ unsigned           g_count;            // last-block counter

__device__ __forceinline__ unsigned hash_cell(unsigned cell) {
    return (cell * 2654435761u) >> (32 - HLOG2);
}

// ================= K1: per-edge last-write-wins hash insert =================
// JAX .at[...].set with duplicate indices: last update (largest e) wins.
__global__ void k_insert(const int* __restrict__ ei) {
    int t = blockIdx.x * blockDim.x + threadIdx.x;
    if (t >= TOT_EDGES) return;
    int b = t / NEDGE;
    int e = t - b * NEDGE;
    int i = ei[t] % NB;              if (i < 0) i += NB;
    int j = ei[TOT_EDGES + t] % NB;  if (j < 0) j += NB;

    unsigned cell = (unsigned)(i * NB + j) + 1u;            // +1 so 0 == empty
    unsigned long long mine = ((unsigned long long)cell << 32) | (unsigned)e;
    unsigned h = hash_cell(cell);
    unsigned long long* tab = g_hash + ((size_t)b << HLOG2);

    while (true) {
        unsigned long long old = atomicCAS(&tab[h], 0ULL, mine);
        if (old == 0ULL) break;                              // claimed empty slot
        if ((unsigned)(old >> 32) == cell) {                 // same cell: max e wins
            atomicMax(&tab[h], mine);
            break;
        }
        h = (h + 1) & HMASK;                                 // linear probe
    }
}

// ====== K2: slot scan -> scatter adm*V[j] into YV[b,i]; self-clean slot ======
// Each slot is read by exactly one thread, so zeroing it here is safe and
// restores g_hash for the next call.
__global__ void k_scatter(const float* __restrict__ ea,
                          const float* __restrict__ outs) {
    int s = blockIdx.x * blockDim.x + threadIdx.x;
    if (s >= TOT_SLOTS) return;
    unsigned long long ent = g_hash[s];
    if (ent == 0ULL) return;
    g_hash[s] = 0ULL;                                        // self-clean

    int b = s >> HLOG2;
    unsigned cell = (unsigned)(ent >> 32) - 1u;
    int e = (int)(unsigned)ent;
    int i = (int)(cell / NB);
    int j = (int)(cell - (unsigned)i * NB);

    float2 adm = ((const float2*)ea)[b * NEDGE + e];
    float2 v   = ((const float2*)outs)[b * NB + j];
    int ni = b * NB + i;
    atomicAdd(&g_yv[ni].x, adm.x * v.x - adm.y * v.y);
    atomicAdd(&g_yv[ni].y, adm.x * v.y + adm.y * v.x);
}

// ========== K3: node terms + reduce + last-block finalize; self-clean =======
// Output: 5 float32 = real parts of (loss, physics_loss, d1, d2, d3).
#define NTHR3 256
#define NBLK3 ((TOT_NODES + NTHR3 - 1) / NTHR3)   // 250

__global__ __launch_bounds__(NTHR3)
void k_node(const float* __restrict__ x,
            const float* __restrict__ outs,
            const float* __restrict__ labels,
            float* __restrict__ out, int nfloats) {
    int idx = blockIdx.x * NTHR3 + threadIdx.x;
    float a0 = 0.f, a1 = 0.f, a2 = 0.f, a3 = 0.f, a4 = 0.f;

    if (idx < TOT_NODES) {
        float2 v  = ((const float2*)outs)[idx];
        float2 yv = g_yv[idx];
        g_yv[idx] = make_float2(0.f, 0.f);                   // self-clean

        // Spred = V * conj(YV)
        float spr = v.x * yv.x + v.y * yv.y;
        float spi = v.y * yv.x - v.x * yv.y;

        const float2* nf2 = (const float2*)(x + 6 * idx);
        float2 p0 = nf2[0], p1 = nf2[1], p2 = nf2[2];
        float sr = p0.x, si = p0.y, Vm = p1.x;
        float b0 = p1.y, b1 = p2.x, b2 = p2.y;

        float dr = spr - sr;
        float di = spi - si;
        float sinv = rsqrtf(sr * sr + si * si);              // |1/S|

        a0 = sinv * ((dr * dr - di * di) * b0 + dr * dr * b1);
        a1 = sinv * (2.f * dr * di * b0);

        float vmag  = sqrtf(v.x * v.x + v.y * v.y);
        float vminv = 1.f / Vm;
        a2 = fabsf(vmag * (b1 + b2) - Vm) * vminv;
        a3 = fabsf(v.y * b2) * vminv;

        float2 lab = ((const float2*)labels)[idx];
        float e0 = v.x - lab.x;
        float e1 = v.y - lab.y;
        a4 = e0 * e0 + e1 * e1;
    }

    // warp reduce (float)
    #pragma unroll
    for (int o = 16; o > 0; o >>= 1) {
        a0 += __shfl_down_sync(0xFFFFFFFFu, a0, o);
        a1 += __shfl_down_sync(0xFFFFFFFFu, a1, o);
        a2 += __shfl_down_sync(0xFFFFFFFFu, a2, o);
        a3 += __shfl_down_sync(0xFFFFFFFFu, a3, o);
        a4 += __shfl_down_sync(0xFFFFFFFFu, a4, o);
    }

    __shared__ float sm[5][8];
    __shared__ bool  last;
    int lane = threadIdx.x & 31, warp = threadIdx.x >> 5;
    if (lane == 0) { sm[0][warp] = a0; sm[1][warp] = a1; sm[2][warp] = a2;
                     sm[3][warp] = a3; sm[4][warp] = a4; }
    __syncthreads();
    if (warp == 0) {
        float v0 = (lane < 8) ? sm[0][lane] : 0.f;
        float v1 = (lane < 8) ? sm[1][lane] : 0.f;
        float v2 = (lane < 8) ? sm[2][lane] : 0.f;
        float v3 = (lane < 8) ? sm[3][lane] : 0.f;
        float v4 = (lane < 8) ? sm[4][lane] : 0.f;
        #pragma unroll
        for (int o = 4; o > 0; o >>= 1) {
            v0 += __shfl_down_sync(0xFFFFFFFFu, v0, o);
            v1 += __shfl_down_sync(0xFFFFFFFFu, v1, o);
            v2 += __shfl_down_sync(0xFFFFFFFFu, v2, o);
            v3 += __shfl_down_sync(0xFFFFFFFFu, v3, o);
            v4 += __shfl_down_sync(0xFFFFFFFFu, v4, o);
        }
        if (lane == 0) {
            atomicAdd(&g_acc[0], v0);
            atomicAdd(&g_acc[1], v1);
            atomicAdd(&g_acc[2], v2);
            atomicAdd(&g_acc[3], v3);
            atomicAdd(&g_acc[4], v4);
            __threadfence();
            unsigned r = atomicAdd(&g_count, 1u);
            last = (r == (unsigned)(gridDim.x - 1));
        }
    }
    __syncthreads();

    if (last && threadIdx.x == 0) {
        // atomics live in L2; bypass (possibly stale) L1
        float v0 = __ldcg(&g_acc[0]);
        float v1 = __ldcg(&g_acc[1]);
        float v2 = __ldcg(&g_acc[2]);
        float v3 = __ldcg(&g_acc[3]);
        float v4 = __ldcg(&g_acc[4]);
        const double inv = 1.0 / (double)TOT_NODES;
        double d1r = (double)v0 * inv;
        double d1i = (double)v1 * inv;
        double d2  = (double)v2 * inv;
        double d3  = (double)v3 * inv;
        double mse = (double)v4 / (double)(TOT_NODES * 2);
        double pr  = d1r + d2 + d3;
        double lr  = mse + 0.1 * pr;
        float vals[10] = { (float)lr, (float)pr, (float)d1r, (float)d2, (float)d3,
                           (float)(0.1 * d1i), (float)d1i, (float)d1i, 0.f, 0.f };
        for (int k = 0; k < nfloats && k < 10; k++) out[k] = vals[k];
        // self-clean accumulators for the next call
        g_acc[0] = 0.f; g_acc[1] = 0.f; g_acc[2] = 0.f;
        g_acc[3] = 0.f; g_acc[4] = 0.f;
        g_count  = 0u;
    }
}

// ------------------------------------------------------------------ launcher
extern "C" void kernel_launch(void* const* d_in, const int* in_sizes, int n_in,
                              void* d_out, int out_size) {
    const float* x      = (const float*)d_in[0];   // (B*2000, 6)
    const float* ea     = (const float*)d_in[1];   // (B*6000, 2)
    const int*   ei     = (const int*)  d_in[2];   // (2, B*6000)
    const float* outs   = (const float*)d_in[3];   // (B*2000, 2)
    const float* labels = (const float*)d_in[4];   // (B*2000, 2)
    (void)in_sizes; (void)n_in;

    int nfloats = out_size < 10 ? out_size : 10;

    k_insert <<<(TOT_EDGES + 255) / 256, 256>>>(ei);
    k_scatter<<<(TOT_SLOTS + 255) / 256, 256>>>(ea, outs);
    k_node   <<<NBLK3, NTHR3>>>(x, outs, labels, (float*)d_out, nfloats);
}

// round 6
// speedup vs baseline: 3.8443x; 2.5849x over previous
#include <cuda_runtime.h>

// Problem constants (fixed by the reference)
#define NB        2000                  // N_BUSES
#define BATCH     32                    // B
#define NEDGE     6000                  // E per batch
#define TOT_NODES (BATCH * NB)          // 64000
#define TOT_EDGES (BATCH * NEDGE)       // 192000
#define HLOG2     14
#define HSLOTS    16384                 // per-batch slots, load 0.37 (R2-proven)
#define HMASK     (HSLOTS - 1)
#define TOT_SLOTS (BATCH * HSLOTS)      // 524288 (4 MB)

// Static scratch — zero at module load; every kernel self-cleans what it used,
// so each kernel_launch call starts from zeroed state (deterministic).
__device__ unsigned long long g_hash[TOT_SLOTS];  // (cell+1)<<32 | edge_id
__device__ float2             g_yv[TOT_NODES];    // YV (complex)
__device__ float              g_acc[5];           // d1r, d1i, d2, d3, mse
__device__ unsigned           g_count;            // last-block counter

// R2-proven hash: low bits of multiplicative hash.
__device__ __forceinline__ unsigned hash_cell(unsigned cell) {
    return (cell * 2654435761u) & HMASK;
}

// ================= K1: per-edge last-write-wins hash insert =================
// JAX .at[...].set with duplicate indices: last update (largest e) wins.
__global__ void k_insert(const int* __restrict__ ei) {
    int t = blockIdx.x * blockDim.x + threadIdx.x;
    if (t >= TOT_EDGES) return;
    int b = t / NEDGE;
    int e = t - b * NEDGE;
    int i = ei[t] % NB;              if (i < 0) i += NB;
    int j = ei[TOT_EDGES + t] % NB;  if (j < 0) j += NB;

    unsigned cell = (unsigned)(i * NB + j) + 1u;            // +1 so 0 == empty
    unsigned long long mine = ((unsigned long long)cell << 32) | (unsigned)e;
    unsigned h = hash_cell(cell);
    unsigned long long* tab = g_hash + ((size_t)b << HLOG2);

    while (true) {
        unsigned long long old = atomicCAS(&tab[h], 0ULL, mine);
        if (old == 0ULL) break;                              // claimed empty slot
        if ((unsigned)(old >> 32) == cell) {                 // same cell: max e wins
            atomicMax(&tab[h], mine);
            break;
        }
        h = (h + 1) & HMASK;                                 // linear probe
    }
}

// ====== K2: slot scan -> scatter adm*V[j] into YV[b,i]; self-clean slot ======
// Each slot is read by exactly one thread, so zeroing it here is safe and
// restores g_hash for the next call.
__global__ void k_scatter(const float* __restrict__ ea,
                          const float* __restrict__ outs) {
    int s = blockIdx.x * blockDim.x + threadIdx.x;
    if (s >= TOT_SLOTS) return;
    unsigned long long ent = g_hash[s];
    if (ent == 0ULL) return;
    g_hash[s] = 0ULL;                                        // self-clean

    int b = s >> HLOG2;
    unsigned cell = (unsigned)(ent >> 32) - 1u;
    int e = (int)(unsigned)ent;
    int i = (int)(cell / NB);
    int j = (int)(cell - (unsigned)i * NB);

    float2 adm = ((const float2*)ea)[b * NEDGE + e];
    float2 v   = ((const float2*)outs)[b * NB + j];
    int ni = b * NB + i;
    atomicAdd(&g_yv[ni].x, adm.x * v.x - adm.y * v.y);
    atomicAdd(&g_yv[ni].y, adm.x * v.y + adm.y * v.x);
}

// ========== K3: node terms + reduce + last-block finalize; self-clean =======
// Output: 5 float32 = real parts of (loss, physics_loss, d1, d2, d3).
#define NTHR3 256
#define NBLK3 ((TOT_NODES + NTHR3 - 1) / NTHR3)   // 250

__global__ __launch_bounds__(NTHR3)
void k_node(const float* __restrict__ x,
            const float* __restrict__ outs,
            const float* __restrict__ labels,
            float* __restrict__ out, int nfloats) {
    int idx = blockIdx.x * NTHR3 + threadIdx.x;
    float a0 = 0.f, a1 = 0.f, a2 = 0.f, a3 = 0.f, a4 = 0.f;

    if (idx < TOT_NODES) {
        float2 v  = ((const float2*)outs)[idx];
        float2 yv = g_yv[idx];
        g_yv[idx] = make_float2(0.f, 0.f);                   // self-clean

        // Spred = V * conj(YV)
        float spr = v.x * yv.x + v.y * yv.y;
        float spi = v.y * yv.x - v.x * yv.y;

        const float2* nf2 = (const float2*)(x + 6 * idx);
        float2 p0 = nf2[0], p1 = nf2[1], p2 = nf2[2];
        float sr = p0.x, si = p0.y, Vm = p1.x;
        float b0 = p1.y, b1 = p2.x, b2 = p2.y;

        float dr = spr - sr;
        float di = spi - si;
        float sinv = rsqrtf(sr * sr + si * si);              // |1/S|

        a0 = sinv * ((dr * dr - di * di) * b0 + dr * dr * b1);
        a1 = sinv * (2.f * dr * di * b0);

        float vmag  = sqrtf(v.x * v.x + v.y * v.y);
        float vminv = 1.f / Vm;
        a2 = fabsf(vmag * (b1 + b2) - Vm) * vminv;
        a3 = fabsf(v.y * b2) * vminv;

        float2 lab = ((const float2*)labels)[idx];
        float e0 = v.x - lab.x;
        float e1 = v.y - lab.y;
        a4 = e0 * e0 + e1 * e1;
    }

    // warp reduce (float)
    #pragma unroll
    for (int o = 16; o > 0; o >>= 1) {
        a0 += __shfl_down_sync(0xFFFFFFFFu, a0, o);
        a1 += __shfl_down_sync(0xFFFFFFFFu, a1, o);
        a2 += __shfl_down_sync(0xFFFFFFFFu, a2, o);
        a3 += __shfl_down_sync(0xFFFFFFFFu, a3, o);
        a4 += __shfl_down_sync(0xFFFFFFFFu, a4, o);
    }

    __shared__ float sm[5][8];
    __shared__ bool  last;
    int lane = threadIdx.x & 31, warp = threadIdx.x >> 5;
    if (lane == 0) { sm[0][warp] = a0; sm[1][warp] = a1; sm[2][warp] = a2;
                     sm[3][warp] = a3; sm[4][warp] = a4; }
    __syncthreads();
    if (warp == 0) {
        float v0 = (lane < 8) ? sm[0][lane] : 0.f;
        float v1 = (lane < 8) ? sm[1][lane] : 0.f;
        float v2 = (lane < 8) ? sm[2][lane] : 0.f;
        float v3 = (lane < 8) ? sm[3][lane] : 0.f;
        float v4 = (lane < 8) ? sm[4][lane] : 0.f;
        #pragma unroll
        for (int o = 4; o > 0; o >>= 1) {
            v0 += __shfl_down_sync(0xFFFFFFFFu, v0, o);
            v1 += __shfl_down_sync(0xFFFFFFFFu, v1, o);
            v2 += __shfl_down_sync(0xFFFFFFFFu, v2, o);
            v3 += __shfl_down_sync(0xFFFFFFFFu, v3, o);
            v4 += __shfl_down_sync(0xFFFFFFFFu, v4, o);
        }
        if (lane == 0) {
            atomicAdd(&g_acc[0], v0);
            atomicAdd(&g_acc[1], v1);
            atomicAdd(&g_acc[2], v2);
            atomicAdd(&g_acc[3], v3);
            atomicAdd(&g_acc[4], v4);
            __threadfence();
            unsigned r = atomicAdd(&g_count, 1u);
            last = (r == (unsigned)(gridDim.x - 1));
        }
    }
    __syncthreads();

    if (last && threadIdx.x == 0) {
        // atomics live in L2; bypass (possibly stale) L1
        float v0 = __ldcg(&g_acc[0]);
        float v1 = __ldcg(&g_acc[1]);
        float v2 = __ldcg(&g_acc[2]);
        float v3 = __ldcg(&g_acc[3]);
        float v4 = __ldcg(&g_acc[4]);
        const double inv = 1.0 / (double)TOT_NODES;
        double d1r = (double)v0 * inv;
        double d1i = (double)v1 * inv;
        double d2  = (double)v2 * inv;
        double d3  = (double)v3 * inv;
        double mse = (double)v4 / (double)(TOT_NODES * 2);
        double pr  = d1r + d2 + d3;
        double lr  = mse + 0.1 * pr;
        float vals[10] = { (float)lr, (float)pr, (float)d1r, (float)d2, (float)d3,
                           (float)(0.1 * d1i), (float)d1i, (float)d1i, 0.f, 0.f };
        for (int k = 0; k < nfloats && k < 10; k++) out[k] = vals[k];
        // self-clean accumulators for the next call
        g_acc[0] = 0.f; g_acc[1] = 0.f; g_acc[2] = 0.f;
        g_acc[3] = 0.f; g_acc[4] = 0.f;
        g_count  = 0u;
    }
}

// ------------------------------------------------------------------ launcher
extern "C" void kernel_launch(void* const* d_in, const int* in_sizes, int n_in,
                              void* d_out, int out_size) {
    const float* x      = (const float*)d_in[0];   // (B*2000, 6)
    const float* ea     = (const float*)d_in[1];   // (B*6000, 2)
    const int*   ei     = (const int*)  d_in[2];   // (2, B*6000)
    const float* outs   = (const float*)d_in[3];   // (B*2000, 2)
    const float* labels = (const float*)d_in[4];   // (B*2000, 2)
    (void)in_sizes; (void)n_in;

    int nfloats = out_size < 10 ? out_size : 10;

    k_insert <<<(TOT_EDGES + 255) / 256, 256>>>(ei);
    k_scatter<<<(TOT_SLOTS + 255) / 256, 256>>>(ea, outs);
    k_node   <<<NBLK3, NTHR3>>>(x, outs, labels, (float*)d_out, nfloats);
}